// round 16
// baseline (speedup 1.0000x reference)
#include <cuda_runtime.h>
#include <cuda_pipeline.h>
#include <cuda.h>
#include <cstdint>

// Fused YOLO decode, single launch, TMA-staged 52-cell tiles.
//
// Scales 52/26: one cp.async.bulk.tensor.2d per block loads a [45 ch x 52
// cell] tile (9360 B; box row 208 B, 16B-legal; global row strides
// 10816/2704 B, 16B-legal). TPB=160 -> all 156 output rows decode in ONE
// iteration; small smem -> ~10-12 independent CTAs/SM.
// Scale 13 (row stride 676 B, TMA-illegal): anchor-split cp.async path.
// Output: boxes [N,6] in scale order 13,26,52, then mask [N].

#define TPB 160
#define NCH 45
#define TILEC 52
#define TR (TILEC * 3)            // 156 rows per tile

#define B52T 6656   // 128 images * 52 tiles
#define B26T 1664   // 128 images * 13 tiles
#define B13  384    // 128 images * 3 anchors

#define ROWS13 64896
#define ROWS26 259584
#define ROWS52 1038336
#define ROWBASE13 0
#define ROWBASE26 ROWS13
#define ROWBASE52 (ROWS13 + ROWS26)

#define SMEM_FLOATS 2540          // max(45*52=2340, scale13 superset 635*4)

__device__ __forceinline__ uint32_t smem_u32(const void* p) {
    return (uint32_t)__cvta_generic_to_shared(p);
}

// ---- TMA tile path: load [45 x 52] tile, decode 156 rows ----
template<int W, int STRIDE>
__device__ __forceinline__ void tma_path(const CUtensorMap* __restrict__ map,
                                         const float* __restrict__ anchors,
                                         float thr,
                                         float* __restrict__ boxes,
                                         float* __restrict__ mask,
                                         size_t rowbase,
                                         int blk, int t,
                                         float* __restrict__ s,
                                         unsigned long long* __restrict__ mbar)
{
    constexpr int HW  = W * W;
    constexpr int TPI = HW / TILEC;           // exact (52 | 676 | 2704)
    constexpr uint32_t TBYTES = NCH * TILEC * 4;

    const int b  = blk / TPI;
    const int j  = blk - b * TPI;
    const int t0 = j * TILEC;

    const uint32_t mb = smem_u32(mbar);
    const uint32_t sa = smem_u32(s);

    if (t == 0) {
        asm volatile("mbarrier.init.shared::cta.b64 [%0], %1;"
                     :: "r"(mb), "r"(1) : "memory");
    }
    __syncthreads();

    if (t == 0) {
        asm volatile("mbarrier.arrive.expect_tx.shared::cta.b64 _, [%0], %1;"
                     :: "r"(mb), "r"(TBYTES) : "memory");
        asm volatile(
            "cp.async.bulk.tensor.2d.shared::cta.global.tile.mbarrier::complete_tx::bytes "
            "[%0], [%1, {%2, %3}], [%4];"
            :: "r"(sa), "l"(map), "r"(t0), "r"(b * NCH), "r"(mb)
            : "memory");
    }

    // wait for TMA completion, phase 0, HW-sleep hint to spare issue slots
    {
        uint32_t done = 0;
        while (!done) {
            asm volatile(
                "{\n\t.reg .pred p;\n\t"
                "mbarrier.try_wait.parity.shared::cta.b64 p, [%1], %2, 0x989680;\n\t"
                "selp.b32 %0, 1, 0, p;\n\t}"
                : "=r"(done) : "r"(mb), "r"(0) : "memory");
        }
    }

    // ---- decode: thread t -> row t (single pass, 156 < 160) ----
    if (t >= TR) return;

    const int lc = t / 3;
    const int a  = t - 3 * lc;

    const float* sc = s + (a * 15) * TILEC + lc;

    const float o0 = sc[0 * TILEC];
    const float o1 = sc[1 * TILEC];
    const float o2 = sc[2 * TILEC];
    const float o3 = sc[3 * TILEC];
    const float o4 = sc[4 * TILEC];

    float best = sc[5 * TILEC];
    int bi = 0;
    #pragma unroll
    for (int c = 1; c < 10; ++c) {
        const float q = sc[(5 + c) * TILEC];
        if (q > best) { best = q; bi = c; }
    }

    const int cw = t0 + lc;
    const int h  = cw / W;
    const int w  = cw - h * W;

    const float px = ((float)w + o1) * (float)STRIDE;
    const float py = ((float)h + o2) * (float)STRIDE;
    const float pw = __ldg(anchors + 2 * a + 0) * __expf(o3);
    const float ph = __ldg(anchors + 2 * a + 1) * __expf(o4);

    const size_t orow = rowbase + ((size_t)b * HW + t0) * 3 + t;
    float2* ob = (float2*)(boxes + orow * 6);
    ob[0] = make_float2(o0,              px - 0.5f * pw);
    ob[1] = make_float2(py - 0.5f * ph,  px + 0.5f * pw);
    ob[2] = make_float2(py + 0.5f * ph,  (float)bi);

    mask[orow] = (o0 > thr) ? 1.0f : 0.0f;
}

__global__ __launch_bounds__(TPB)
void decode_fused_kernel(const float* __restrict__ in13,
                         const float* __restrict__ anc13,
                         const float* __restrict__ anc26,
                         const float* __restrict__ anc52,
                         const float* __restrict__ thresh_p,
                         float* __restrict__ boxes,
                         float* __restrict__ mask,
                         const __grid_constant__ CUtensorMap map26,
                         const __grid_constant__ CUtensorMap map52)
{
    __shared__ alignas(128) float s[SMEM_FLOATS];
    __shared__ alignas(8) unsigned long long mbar;

    const int bid = blockIdx.x;
    const int t = threadIdx.x;
    const float thr = __ldg(thresh_p);

    if (bid < B52T) {
        tma_path<52, 8>(&map52, anc52, thr, boxes, mask,
                        (size_t)ROWBASE52, bid, t, s, &mbar);
    } else if (bid < B52T + B26T) {
        tma_path<26, 16>(&map26, anc26, thr, boxes, mask,
                         (size_t)ROWBASE26, bid - B52T, t, s, &mbar);
    } else {
        // ---- scale 13: anchor-split cp.async (proven path) ----
        const int blk = bid - (B52T + B26T);    // = 3*b + a
        const int b = blk / 3;
        const int a = blk - 3 * b;

        const int m = (3 * blk) & 3;            // 2535 % 4 == 3
        const size_t off = (size_t)2535 * blk;
        const float4* src4 = (const float4*)in13 + (off - m) / 4;
        const int nf4 = (m + 2535 + 3) >> 2;    // 634 or 635

        float4* s4 = (float4*)s;
        #pragma unroll
        for (int k = 0; k < 4; ++k) {
            const int r = t + k * TPB;
            if (k == 3 && r >= nf4) break;
            __pipeline_memcpy_async(&s4[r], src4 + r, 16);
        }
        __pipeline_commit();
        __pipeline_wait_prior(0);
        __syncthreads();

        const float aw = __ldg(anc13 + 2 * a + 0);
        const float ah = __ldg(anc13 + 2 * a + 1);

        #pragma unroll
        for (int k = 0; k < 2; ++k) {
            const int lc = t + k * TPB;
            if (k == 1 && lc >= 169) break;

            const float* sc = s + m + lc;

            const float o0 = sc[0 * 169];
            const float o1 = sc[1 * 169];
            const float o2 = sc[2 * 169];
            const float o3 = sc[3 * 169];
            const float o4 = sc[4 * 169];

            float best = sc[5 * 169];
            int bi = 0;
            #pragma unroll
            for (int c = 1; c < 10; ++c) {
                const float q = sc[(5 + c) * 169];
                if (q > best) { best = q; bi = c; }
            }

            const int h = lc / 13;
            const int w = lc - h * 13;

            const float px = ((float)w + o1) * 32.0f;
            const float py = ((float)h + o2) * 32.0f;
            const float pw = aw * __expf(o3);
            const float ph = ah * __expf(o4);

            const size_t orow = (size_t)ROWBASE13 + ((size_t)b * 169 + lc) * 3 + a;
            float2* ob = (float2*)(boxes + orow * 6);
            ob[0] = make_float2(o0,              px - 0.5f * pw);
            ob[1] = make_float2(py - 0.5f * ph,  px + 0.5f * pw);
            ob[2] = make_float2(py + 0.5f * ph,  (float)bi);

            mask[orow] = (o0 > thr) ? 1.0f : 0.0f;
        }
    }
}

// ---- host: tensormap via runtime-queried driver entry point (no -lcuda) ----
typedef CUresult (*PFN_encode_t)(
    CUtensorMap*, CUtensorMapDataType, cuuint32_t, void*,
    const cuuint64_t*, const cuuint64_t*, const cuuint32_t*, const cuuint32_t*,
    CUtensorMapInterleave, CUtensorMapSwizzle, CUtensorMapL2promotion,
    CUtensorMapFloatOOBfill);

static PFN_encode_t get_encoder()
{
    static PFN_encode_t fn = nullptr;
    if (!fn) {
        void* p = nullptr;
#if CUDART_VERSION >= 12050
        cudaDriverEntryPointQueryResult qr;
        cudaGetDriverEntryPointByVersion("cuTensorMapEncodeTiled", &p, 12000,
                                         cudaEnableDefault, &qr);
#else
        cudaGetDriverEntryPoint("cuTensorMapEncodeTiled", &p, cudaEnableDefault);
#endif
        fn = (PFN_encode_t)p;
    }
    return fn;
}

static void make_map(CUtensorMap* m, const void* ptr, uint64_t hw, uint32_t boxw)
{
    cuuint64_t dims[2]    = { hw, (cuuint64_t)(NCH * 128) };
    cuuint64_t strides[1] = { hw * 4 };           // bytes; 16B multiple
    cuuint32_t box[2]     = { boxw, NCH };
    cuuint32_t estr[2]    = { 1, 1 };
    get_encoder()(m, CU_TENSOR_MAP_DATA_TYPE_FLOAT32, 2, const_cast<void*>(ptr),
                  dims, strides, box, estr,
                  CU_TENSOR_MAP_INTERLEAVE_NONE, CU_TENSOR_MAP_SWIZZLE_NONE,
                  CU_TENSOR_MAP_L2_PROMOTION_L2_128B,
                  CU_TENSOR_MAP_FLOAT_OOB_FILL_NONE);
}

extern "C" void kernel_launch(void* const* d_in, const int* in_sizes, int n_in,
                              void* d_out, int out_size)
{
    const float* out13 = (const float*)d_in[0];
    const float* out26 = (const float*)d_in[1];
    const float* out52 = (const float*)d_in[2];
    const float* anc13 = (const float*)d_in[3];
    const float* anc26 = (const float*)d_in[4];
    const float* anc52 = (const float*)d_in[5];
    const float* thr   = (const float*)d_in[6];

    float* out = (float*)d_out;
    const int rowsTot = ROWS13 + ROWS26 + ROWS52;   // 1,362,816

    float* boxes = out;                       // [rowsTot, 6]
    float* mask  = out + (size_t)rowsTot * 6; // [rowsTot]

    CUtensorMap map26, map52;
    make_map(&map26, out26, 676,  TILEC);
    make_map(&map52, out52, 2704, TILEC);

    decode_fused_kernel<<<B52T + B26T + B13, TPB>>>(
        out13, anc13, anc26, anc52, thr, boxes, mask, map26, map52);
}